// round 1
// baseline (speedup 1.0000x reference)
#include <cuda_runtime.h>
#include <cuda_bf16.h>
#include <mma.h>

using namespace nvcuda;

#define NTOK 16384
#define DIM  1024
#define FF   4096
#define NE   8
#define CAP  2560
#define NB_M 40          // CAP / 64

// ---------------- scratch (device globals; no allocation allowed) ----------
__device__ __nv_bfloat16 g_xb[(size_t)NTOK * DIM];
__device__ __nv_bfloat16 g_wg[(size_t)NE * DIM * FF];
__device__ __nv_bfloat16 g_wu[(size_t)NE * DIM * FF];
__device__ __nv_bfloat16 g_wd[(size_t)NE * FF * DIM];
__device__ __nv_bfloat16 g_h[(size_t)NE * CAP * FF];
__device__ float g_ffn[(size_t)NTOK * DIM];
__device__ int   g_top1[NTOK];
__device__ float g_topv[NTOK];
__device__ int   g_dest[NE * CAP];
__device__ int   g_rows[NE];
__device__ int   g_cnt[NE];
__device__ float g_sumP[NE];

// ---------------- small helpers --------------------------------------------
__global__ void k_init() {
    int t = threadIdx.x;
    if (t < NE) g_sumP[t] = 0.f;
}

// fp32 -> bf16 conversion into one of the scratch buffers (sel selects target)
__global__ void k_convert(const float* __restrict__ in, int n, int sel) {
    __nv_bfloat16* out = (sel == 0) ? g_xb : (sel == 1) ? g_wg : (sel == 2) ? g_wu : g_wd;
    int stride = gridDim.x * blockDim.x * 4;
    for (int i = (blockIdx.x * blockDim.x + threadIdx.x) * 4; i < n; i += stride) {
        float4 v = *(const float4*)(in + i);
        __nv_bfloat162 a = __floats2bfloat162_rn(v.x, v.y);
        __nv_bfloat162 b = __floats2bfloat162_rn(v.z, v.w);
        *(__nv_bfloat162*)(out + i)     = a;
        *(__nv_bfloat162*)(out + i + 2) = b;
    }
}

__global__ void k_zero_ffn() {
    int stride = gridDim.x * blockDim.x * 4;
    float4 z = make_float4(0.f, 0.f, 0.f, 0.f);
    for (int i = (blockIdx.x * blockDim.x + threadIdx.x) * 4; i < NTOK * DIM; i += stride)
        *(float4*)(g_ffn + i) = z;
}

// ---------------- router: logits, softmax, top-1, prob sums ----------------
__global__ void __launch_bounds__(256) k_router(const float* __restrict__ x,
                                                const float* __restrict__ rw) {
    __shared__ float rws[DIM * NE];   // 32 KB
    __shared__ float blockP[NE];
    int tid = threadIdx.x;
    for (int i = tid; i < DIM * NE; i += 256) rws[i] = rw[i];
    if (tid < NE) blockP[tid] = 0.f;
    __syncthreads();

    int warp = tid >> 5, lane = tid & 31;
    int token = blockIdx.x * 8 + warp;

    float acc[NE];
#pragma unroll
    for (int e = 0; e < NE; e++) acc[e] = 0.f;
    const float* xr = x + (size_t)token * DIM;
    for (int i = lane; i < DIM; i += 32) {
        float xv = xr[i];
#pragma unroll
        for (int e = 0; e < NE; e++) acc[e] += xv * rws[i * NE + e];
    }
#pragma unroll
    for (int e = 0; e < NE; e++)
#pragma unroll
        for (int o = 16; o; o >>= 1) acc[e] += __shfl_xor_sync(0xffffffffu, acc[e], o);

    if (lane == 0) {
        float m = acc[0]; int am = 0;
#pragma unroll
        for (int e = 1; e < NE; e++) if (acc[e] > m) { m = acc[e]; am = e; }
        float p[NE], s = 0.f;
#pragma unroll
        for (int e = 0; e < NE; e++) { p[e] = __expf(acc[e] - m); s += p[e]; }
        float inv = 1.f / s;
        g_top1[token] = am;
        g_topv[token] = p[am] * inv;
#pragma unroll
        for (int e = 0; e < NE; e++) atomicAdd(&blockP[e], p[e] * inv);
    }
    __syncthreads();
    if (tid < NE) atomicAdd(&g_sumP[tid], blockP[tid]);
}

// ---------------- deterministic token-order scan + dispatch list -----------
__global__ void k_scan() {
    __shared__ int ids[256];
    __shared__ int base[NE];
    __shared__ int wc[NE];
    int tid = threadIdx.x;
    if (tid < NE) base[tid] = 0;
    __syncthreads();
    for (int w = 0; w < NTOK / 256; w++) {
        int t = w * 256 + tid;
        ids[tid] = g_top1[t];
        __syncthreads();
        int e = ids[tid];
        int r = 0;
        for (int j = 0; j < tid; j++) r += (ids[j] == e);
        if (tid < NE) {
            int c = 0;
            for (int j = 0; j < 256; j++) c += (ids[j] == tid);
            wc[tid] = c;
        }
        int p = base[e] + r;
        if (p < CAP) g_dest[e * CAP + p] = t;
        __syncthreads();
        if (tid < NE) base[tid] += wc[tid];
        __syncthreads();
    }
    if (tid < NE) {
        g_cnt[tid] = base[tid];
        g_rows[tid] = min(base[tid], CAP);
    }
}

// ---------------- GEMM1: h = silu(X Wg) * (X Wu), gathered rows ------------
// tile M=64, N=64 (per matrix), K=32; 8 warps: warps 0-3 -> gate, 4-7 -> up
__global__ void __launch_bounds__(256) k_gemm1() {
    extern __shared__ char smem[];
    __nv_bfloat16* As  = (__nv_bfloat16*)smem;   // 64 x 40
    __nv_bfloat16* Bgs = As + 64 * 40;           // 32 x 72
    __nv_bfloat16* Bus = Bgs + 32 * 72;          // 32 x 72
    float* Cs = (float*)smem;                    // reused: 2 x 64 x 64 fp32

    int e = blockIdx.x / NB_M;
    int mrow0 = (blockIdx.x % NB_M) * 64;
    int rows = g_rows[e];
    if (mrow0 >= rows) return;
    int n0 = blockIdx.y * 64;
    int tid = threadIdx.x, warp = tid >> 5;

    int arow = tid >> 2;
    int acol = (tid & 3) * 8;
    int grow = mrow0 + arow;
    int token = (grow < rows) ? g_dest[e * CAP + grow] : 0;
    const __nv_bfloat16* aptr = g_xb + (size_t)token * DIM + acol;

    int brow = tid >> 3;
    int bcol = (tid & 7) * 8;
    size_t wbase = (size_t)e * DIM * FF + (size_t)brow * FF + n0 + bcol;
    const __nv_bfloat16* gptr = g_wg + wbase;
    const __nv_bfloat16* uptr = g_wu + wbase;

    wmma::fragment<wmma::accumulator, 16, 16, 16, float> acc[2][2];
#pragma unroll
    for (int i = 0; i < 2; i++)
#pragma unroll
        for (int j = 0; j < 2; j++) wmma::fill_fragment(acc[i][j], 0.f);

    int mat = warp >> 2;
    int wq = warp & 3;
    int wr = (wq >> 1) * 32;
    int wc0 = (wq & 1) * 32;
    const __nv_bfloat16* Bsrc = mat ? Bus : Bgs;

    for (int k0 = 0; k0 < DIM; k0 += 32) {
        *(uint4*)(As + arow * 40 + acol)  = *(const uint4*)(aptr + k0);
        *(uint4*)(Bgs + brow * 72 + bcol) = *(const uint4*)(gptr + (size_t)k0 * FF);
        *(uint4*)(Bus + brow * 72 + bcol) = *(const uint4*)(uptr + (size_t)k0 * FF);
        __syncthreads();
#pragma unroll
        for (int kk = 0; kk < 32; kk += 16) {
            wmma::fragment<wmma::matrix_a, 16, 16, 16, __nv_bfloat16, wmma::row_major> af0, af1;
            wmma::fragment<wmma::matrix_b, 16, 16, 16, __nv_bfloat16, wmma::row_major> bf0, bf1;
            wmma::load_matrix_sync(af0, As + (wr + 0) * 40 + kk, 40);
            wmma::load_matrix_sync(af1, As + (wr + 16) * 40 + kk, 40);
            wmma::load_matrix_sync(bf0, Bsrc + kk * 72 + wc0, 72);
            wmma::load_matrix_sync(bf1, Bsrc + kk * 72 + wc0 + 16, 72);
            wmma::mma_sync(acc[0][0], af0, bf0, acc[0][0]);
            wmma::mma_sync(acc[0][1], af0, bf1, acc[0][1]);
            wmma::mma_sync(acc[1][0], af1, bf0, acc[1][0]);
            wmma::mma_sync(acc[1][1], af1, bf1, acc[1][1]);
        }
        __syncthreads();
    }

    float* Cmine = Cs + mat * 4096;
#pragma unroll
    for (int i = 0; i < 2; i++)
#pragma unroll
        for (int j = 0; j < 2; j++)
            wmma::store_matrix_sync(Cmine + (wr + 16 * i) * 64 + wc0 + 16 * j,
                                    acc[i][j], 64, wmma::mem_row_major);
    __syncthreads();

    for (int idx = tid; idx < 4096; idx += 256) {
        int r = idx >> 6, c = idx & 63;
        int gr = mrow0 + r;
        if (gr < rows) {
            float gv = Cs[idx];
            float uv = Cs[4096 + idx];
            float h = gv / (1.f + __expf(-gv)) * uv;
            g_h[((size_t)e * CAP + gr) * FF + n0 + c] = __float2bfloat16(h);
        }
    }
}

// ---------------- GEMM2: y = H Wd, scaled scatter into g_ffn ---------------
// tile M=64, N=128, K=32; 8 warps as 2(M) x 4(N) of 32x32
__global__ void __launch_bounds__(256) k_gemm2() {
    extern __shared__ char smem[];
    __nv_bfloat16* As = (__nv_bfloat16*)smem;   // 64 x 40
    __nv_bfloat16* Bs = As + 64 * 40;           // 32 x 136
    float* Cs = (float*)smem;                   // reused: 64 x 128 fp32

    int e = blockIdx.x / NB_M;
    int mrow0 = (blockIdx.x % NB_M) * 64;
    int rows = g_rows[e];
    if (mrow0 >= rows) return;
    int n0 = blockIdx.y * 128;
    int tid = threadIdx.x, warp = tid >> 5;

    int arow = tid >> 2;
    int acol = (tid & 3) * 8;
    const __nv_bfloat16* aptr = g_h + ((size_t)e * CAP + mrow0 + arow) * FF + acol;

    int brow = tid >> 4;            // 0..15 (each thread loads 2 rows)
    int bcol = (tid & 15) * 8;
    const __nv_bfloat16* bptr = g_wd + (size_t)e * FF * DIM + (size_t)brow * DIM + n0 + bcol;

    wmma::fragment<wmma::accumulator, 16, 16, 16, float> acc[2][2];
#pragma unroll
    for (int i = 0; i < 2; i++)
#pragma unroll
        for (int j = 0; j < 2; j++) wmma::fill_fragment(acc[i][j], 0.f);

    int wr = (warp >> 2) * 32;
    int wc0 = (warp & 3) * 32;

    for (int k0 = 0; k0 < FF; k0 += 32) {
        *(uint4*)(As + arow * 40 + acol) = *(const uint4*)(aptr + k0);
        *(uint4*)(Bs + brow * 136 + bcol)        = *(const uint4*)(bptr + (size_t)k0 * DIM);
        *(uint4*)(Bs + (brow + 16) * 136 + bcol) = *(const uint4*)(bptr + (size_t)(k0 + 16) * DIM);
        __syncthreads();
#pragma unroll
        for (int kk = 0; kk < 32; kk += 16) {
            wmma::fragment<wmma::matrix_a, 16, 16, 16, __nv_bfloat16, wmma::row_major> af0, af1;
            wmma::fragment<wmma::matrix_b, 16, 16, 16, __nv_bfloat16, wmma::row_major> bf0, bf1;
            wmma::load_matrix_sync(af0, As + (wr + 0) * 40 + kk, 40);
            wmma::load_matrix_sync(af1, As + (wr + 16) * 40 + kk, 40);
            wmma::load_matrix_sync(bf0, Bs + kk * 136 + wc0, 136);
            wmma::load_matrix_sync(bf1, Bs + kk * 136 + wc0 + 16, 136);
            wmma::mma_sync(acc[0][0], af0, bf0, acc[0][0]);
            wmma::mma_sync(acc[0][1], af0, bf1, acc[0][1]);
            wmma::mma_sync(acc[1][0], af1, bf0, acc[1][0]);
            wmma::mma_sync(acc[1][1], af1, bf1, acc[1][1]);
        }
        __syncthreads();
    }

#pragma unroll
    for (int i = 0; i < 2; i++)
#pragma unroll
        for (int j = 0; j < 2; j++)
            wmma::store_matrix_sync(Cs + (wr + 16 * i) * 128 + wc0 + 16 * j,
                                    acc[i][j], 128, wmma::mem_row_major);
    __syncthreads();

    for (int idx = tid; idx < 8192; idx += 256) {
        int r = idx >> 7, c = idx & 127;
        int gr = mrow0 + r;
        if (gr < rows) {
            int tok = g_dest[e * CAP + gr];
            g_ffn[(size_t)tok * DIM + n0 + c] = Cs[idx] * g_topv[tok];
        }
    }
}

// ---------------- residual + LayerNorm --------------------------------------
__global__ void __launch_bounds__(256) k_ln(const float* __restrict__ x,
                                            const float* __restrict__ lng,
                                            const float* __restrict__ lnb,
                                            float* __restrict__ out) {
    int t = blockIdx.x, tid = threadIdx.x;
    const float* xr = x + (size_t)t * DIM;
    const float* fr = g_ffn + (size_t)t * DIM;
    float v[4], s = 0.f, s2 = 0.f;
#pragma unroll
    for (int i = 0; i < 4; i++) {
        int c = tid + i * 256;
        float r = xr[c] + fr[c];
        v[i] = r; s += r; s2 += r * r;
    }
#pragma unroll
    for (int o = 16; o; o >>= 1) {
        s  += __shfl_xor_sync(0xffffffffu, s, o);
        s2 += __shfl_xor_sync(0xffffffffu, s2, o);
    }
    __shared__ float sh[16];
    int w = tid >> 5;
    if ((tid & 31) == 0) { sh[w] = s; sh[8 + w] = s2; }
    __syncthreads();
    float S = 0.f, S2 = 0.f;
#pragma unroll
    for (int i = 0; i < 8; i++) { S += sh[i]; S2 += sh[8 + i]; }
    float mu = S * (1.f / DIM);
    float var = S2 * (1.f / DIM) - mu * mu;
    float inv = rsqrtf(var + 1e-5f);
    float* orow = out + (size_t)t * DIM;
#pragma unroll
    for (int i = 0; i < 4; i++) {
        int c = tid + i * 256;
        orow[c] = (v[i] - mu) * inv * lng[c] + lnb[c];
    }
}

// ---------------- load-balance loss ------------------------------------------
__global__ void k_loss(float* __restrict__ out, int out_size) {
    if (threadIdx.x == 0 && blockIdx.x == 0) {
        float lb = 0.f;
        const float invN = 1.f / (float)NTOK;
#pragma unroll
        for (int e = 0; e < NE; e++)
            lb += ((float)g_cnt[e] * invN) * (g_sumP[e] * invN);
        lb *= (float)NE;
        if (out_size > NTOK * DIM) out[NTOK * DIM] = lb;
    }
}

// ---------------- launch ------------------------------------------------------
extern "C" void kernel_launch(void* const* d_in, const int* in_sizes, int n_in,
                              void* d_out, int out_size) {
    const float* x   = (const float*)d_in[0];
    const float* rw  = (const float*)d_in[1];
    const float* gw  = (const float*)d_in[2];
    const float* uw  = (const float*)d_in[3];
    const float* dw  = (const float*)d_in[4];
    const float* lng = (const float*)d_in[5];
    const float* lnb = (const float*)d_in[6];
    float* out = (float*)d_out;
    (void)in_sizes; (void)n_in;

    k_init<<<1, 32>>>();
    k_convert<<<4096, 256>>>(x,  NTOK * DIM, 0);
    k_convert<<<8192, 256>>>(gw, NE * DIM * FF, 1);
    k_convert<<<8192, 256>>>(uw, NE * DIM * FF, 2);
    k_convert<<<8192, 256>>>(dw, NE * FF * DIM, 3);
    k_zero_ffn<<<4096, 256>>>();
    k_router<<<NTOK / 8, 256>>>(x, rw);
    k_scan<<<1, 256>>>();

    dim3 g1(NE * NB_M, FF / 64);
    k_gemm1<<<g1, 256, 32768>>>();
    dim3 g2(NE * NB_M, DIM / 128);
    k_gemm2<<<g2, 256, 32768>>>();

    k_ln<<<NTOK, 256>>>(x, lng, lnb, out);
    k_loss<<<1, 1>>>(out, out_size);
}

// round 3
// speedup vs baseline: 1.1553x; 1.1553x over previous
#include <cuda_runtime.h>
#include <cuda_bf16.h>
#include <mma.h>
#include <cstdint>

using namespace nvcuda;

#define NTOK 16384
#define DIM  1024
#define FF   4096
#define NE   8
#define CAP  2560
#define NBM1 20          // CAP / 128
#define NBM2 20

// ---------------- scratch (device globals; no allocation allowed) ----------
__device__ __nv_bfloat16 g_xb[(size_t)NTOK * DIM];
__device__ __nv_bfloat16 g_wg[(size_t)NE * DIM * FF];
__device__ __nv_bfloat16 g_wu[(size_t)NE * DIM * FF];
__device__ __nv_bfloat16 g_wd[(size_t)NE * FF * DIM];
__device__ __nv_bfloat16 g_h[(size_t)NE * CAP * FF];
__device__ float g_ffn[(size_t)NTOK * DIM];
__device__ int   g_top1[NTOK];
__device__ float g_topv[NTOK];
__device__ int   g_dest[NE * CAP];
__device__ int   g_rows[NE];
__device__ int   g_cnt[NE];
__device__ float g_sumP[NE];

// ---------------- cp.async helpers -----------------------------------------
__device__ __forceinline__ void cp16(void* dst, const void* src) {
    uint32_t d = (uint32_t)__cvta_generic_to_shared(dst);
    asm volatile("cp.async.cg.shared.global [%0], [%1], 16;\n" :: "r"(d), "l"(src));
}
__device__ __forceinline__ void cp_commit() { asm volatile("cp.async.commit_group;\n" ::: "memory"); }
__device__ __forceinline__ void cp_wait1()  { asm volatile("cp.async.wait_group 1;\n" ::: "memory"); }

// ---------------- small helpers --------------------------------------------
__global__ void k_init() {
    int t = threadIdx.x;
    if (t < NE) g_sumP[t] = 0.f;
}

__global__ void k_convert(const float* __restrict__ in, int n, int sel) {
    __nv_bfloat16* out = (sel == 0) ? g_xb : (sel == 1) ? g_wg : (sel == 2) ? g_wu : g_wd;
    int stride = gridDim.x * blockDim.x * 4;
    for (int i = (blockIdx.x * blockDim.x + threadIdx.x) * 4; i < n; i += stride) {
        float4 v = *(const float4*)(in + i);
        __nv_bfloat162 a = __floats2bfloat162_rn(v.x, v.y);
        __nv_bfloat162 b = __floats2bfloat162_rn(v.z, v.w);
        *(__nv_bfloat162*)(out + i)     = a;
        *(__nv_bfloat162*)(out + i + 2) = b;
    }
}

__global__ void k_zero_ffn() {
    int stride = gridDim.x * blockDim.x * 4;
    float4 z = make_float4(0.f, 0.f, 0.f, 0.f);
    for (int i = (blockIdx.x * blockDim.x + threadIdx.x) * 4; i < NTOK * DIM; i += stride)
        *(float4*)(g_ffn + i) = z;
}

// ---------------- router ----------------------------------------------------
__global__ void __launch_bounds__(256) k_router(const float* __restrict__ x,
                                                const float* __restrict__ rw) {
    __shared__ float rws[DIM * NE];
    __shared__ float blockP[NE];
    int tid = threadIdx.x;
    for (int i = tid; i < DIM * NE; i += 256) rws[i] = rw[i];
    if (tid < NE) blockP[tid] = 0.f;
    __syncthreads();

    int warp = tid >> 5, lane = tid & 31;
    int token = blockIdx.x * 8 + warp;

    float acc[NE];
#pragma unroll
    for (int e = 0; e < NE; e++) acc[e] = 0.f;
    const float* xr = x + (size_t)token * DIM;
    for (int i = lane; i < DIM; i += 32) {
        float xv = xr[i];
#pragma unroll
        for (int e = 0; e < NE; e++) acc[e] += xv * rws[i * NE + e];
    }
#pragma unroll
    for (int e = 0; e < NE; e++)
#pragma unroll
        for (int o = 16; o; o >>= 1) acc[e] += __shfl_xor_sync(0xffffffffu, acc[e], o);

    if (lane == 0) {
        float m = acc[0]; int am = 0;
#pragma unroll
        for (int e = 1; e < NE; e++) if (acc[e] > m) { m = acc[e]; am = e; }
        float p[NE], s = 0.f;
#pragma unroll
        for (int e = 0; e < NE; e++) { p[e] = __expf(acc[e] - m); s += p[e]; }
        float inv = 1.f / s;
        g_top1[token] = am;
        g_topv[token] = p[am] * inv;
#pragma unroll
        for (int e = 0; e < NE; e++) atomicAdd(&blockP[e], p[e] * inv);
    }
    __syncthreads();
    if (tid < NE) atomicAdd(&g_sumP[tid], blockP[tid]);
}

// ---------------- deterministic token-order scan ----------------------------
__global__ void k_scan() {
    __shared__ int ids[256];
    __shared__ int base[NE];
    __shared__ int wc[NE];
    int tid = threadIdx.x;
    if (tid < NE) base[tid] = 0;
    __syncthreads();
    for (int w = 0; w < NTOK / 256; w++) {
        int t = w * 256 + tid;
        ids[tid] = g_top1[t];
        __syncthreads();
        int e = ids[tid];
        int r = 0;
        for (int j = 0; j < tid; j++) r += (ids[j] == e);
        if (tid < NE) {
            int c = 0;
            for (int j = 0; j < 256; j++) c += (ids[j] == tid);
            wc[tid] = c;
        }
        int p = base[e] + r;
        if (p < CAP) g_dest[e * CAP + p] = t;
        __syncthreads();
        if (tid < NE) base[tid] += wc[tid];
        __syncthreads();
    }
    if (tid < NE) {
        g_cnt[tid] = base[tid];
        g_rows[tid] = min(base[tid], CAP);
    }
}

// ---------------- GEMM1: h = silu(X Wg) * (X Wu) ----------------------------
// tiles: M=128, N=128 (both gate and up), K=32; 512 threads (16 warps)
// warps 0-7 gate, 8-15 up; each warp computes 32x64 (2x4 frags of 16x16)
#define AS_STRIDE 40
#define BS_STRIDE 136
#define A_STAGE   (128 * AS_STRIDE)
#define B_STAGE   (32 * BS_STRIDE)

__global__ void __launch_bounds__(512, 1) k_gemm1() {
    extern __shared__ char smem[];
    __nv_bfloat16* As = (__nv_bfloat16*)smem;            // 2 stages
    __nv_bfloat16* Bg = As + 2 * A_STAGE;
    __nv_bfloat16* Bu = Bg + 2 * B_STAGE;
    __shared__ const __nv_bfloat16* tokp[128];

    int e = blockIdx.x / NBM1;
    int m0 = (blockIdx.x % NBM1) * 128;
    int rows = g_rows[e];
    if (m0 >= rows) return;
    int n0 = blockIdx.y * 128;
    int tid = threadIdx.x;

    if (tid < 128) {
        int gr = m0 + tid;
        int tok = g_dest[e * CAP + ((gr < rows) ? gr : 0)];
        tokp[tid] = g_xb + (size_t)tok * DIM;
    }
    __syncthreads();

    // per-thread load offsets
    int ar  = tid >> 2;            // A row 0..127
    int ac  = (tid & 3) * 8;       // A col (8 bf16 = 16B)
    int bkr = tid >> 4;            // B k-row 0..31
    int bnc = (tid & 15) * 8;      // B n-col
    const __nv_bfloat16* gbase = g_wg + (size_t)e * DIM * FF + n0 + bnc;
    const __nv_bfloat16* ubase = g_wu + (size_t)e * DIM * FF + n0 + bnc;

    auto load_stage = [&](int s, int k0) {
        cp16(As + s * A_STAGE + ar * AS_STRIDE + ac, tokp[ar] + k0 + ac);
        cp16(Bg + s * B_STAGE + bkr * BS_STRIDE + bnc, gbase + (size_t)(k0 + bkr) * FF);
        cp16(Bu + s * B_STAGE + bkr * BS_STRIDE + bnc, ubase + (size_t)(k0 + bkr) * FF);
        cp_commit();
    };

    wmma::fragment<wmma::accumulator, 16, 16, 16, float> acc[2][4];
#pragma unroll
    for (int i = 0; i < 2; i++)
#pragma unroll
        for (int j = 0; j < 4; j++) wmma::fill_fragment(acc[i][j], 0.f);

    int warp = tid >> 5;
    int mat  = warp >> 3;          // 0=gate 1=up
    int w    = warp & 7;
    int wm   = w >> 1;             // 0..3 -> rows wm*32
    int wn   = w & 1;              // 0..1 -> cols wn*64
    const __nv_bfloat16* Bsel = mat ? Bu : Bg;

    load_stage(0, 0);
    for (int it = 0; it < DIM / 32; it++) {
        int s = it & 1;
        if (it + 1 < DIM / 32) load_stage(s ^ 1, (it + 1) * 32);
        else cp_commit();
        cp_wait1();
        __syncthreads();

        const __nv_bfloat16* Ab = As + s * A_STAGE + (wm * 32) * AS_STRIDE;
        const __nv_bfloat16* Bb = Bsel + s * B_STAGE + wn * 64;
#pragma unroll
        for (int kk = 0; kk < 32; kk += 16) {
            wmma::fragment<wmma::matrix_a, 16, 16, 16, __nv_bfloat16, wmma::row_major> af[2];
            wmma::fragment<wmma::matrix_b, 16, 16, 16, __nv_bfloat16, wmma::row_major> bf[4];
            wmma::load_matrix_sync(af[0], Ab + kk, AS_STRIDE);
            wmma::load_matrix_sync(af[1], Ab + 16 * AS_STRIDE + kk, AS_STRIDE);
#pragma unroll
            for (int j = 0; j < 4; j++)
                wmma::load_matrix_sync(bf[j], Bb + kk * BS_STRIDE + j * 16, BS_STRIDE);
#pragma unroll
            for (int i = 0; i < 2; i++)
#pragma unroll
                for (int j = 0; j < 4; j++)
                    wmma::mma_sync(acc[i][j], af[i], bf[j], acc[i][j]);
        }
        __syncthreads();
    }

    // epilogue in two n-halves, staging through reused smem (2 x 128x64 fp32)
    float* Cg = (float*)smem;
    float* Cu = Cg + 128 * 64;
#pragma unroll
    for (int h = 0; h < 2; h++) {
        if (wn == h) {
            float* dst = mat ? Cu : Cg;
#pragma unroll
            for (int i = 0; i < 2; i++)
#pragma unroll
                for (int j = 0; j < 4; j++)
                    wmma::store_matrix_sync(dst + (wm * 32 + i * 16) * 64 + j * 16,
                                            acc[i][j], 64, wmma::mem_row_major);
        }
        __syncthreads();
        for (int idx = tid; idx < 128 * 64; idx += 512) {
            int r = idx >> 6, c = idx & 63;
            if (m0 + r < rows) {
                float gv = Cg[idx], uv = Cu[idx];
                float hv = gv / (1.f + __expf(-gv)) * uv;
                g_h[((size_t)e * CAP + m0 + r) * FF + n0 + h * 64 + c] = __float2bfloat16(hv);
            }
        }
        __syncthreads();
    }
}

// ---------------- GEMM2: y = H Wd, scaled scatter ---------------------------
// tiles: M=128, N=128, K=32; 256 threads (8 warps: 4m x 2n of 32x64)
__global__ void __launch_bounds__(256, 2) k_gemm2() {
    extern __shared__ char smem[];
    __nv_bfloat16* As = (__nv_bfloat16*)smem;
    __nv_bfloat16* Bs = As + 2 * A_STAGE;
    __shared__ int   stok[128];
    __shared__ float sprob[128];

    int e = blockIdx.x / NBM2;
    int m0 = (blockIdx.x % NBM2) * 128;
    int rows = g_rows[e];
    if (m0 >= rows) return;
    int n0 = blockIdx.y * 128;
    int tid = threadIdx.x;

    if (tid < 128) {
        int gr = m0 + tid;
        int tok = g_dest[e * CAP + ((gr < rows) ? gr : 0)];
        stok[tid] = tok;
        sprob[tid] = g_topv[tok];
    }
    __syncthreads();

    const __nv_bfloat16* Abase = g_h + ((size_t)e * CAP + m0) * FF;
    const __nv_bfloat16* Bbase = g_wd + (size_t)e * FF * DIM + n0;

    auto load_stage = [&](int s, int k0) {
#pragma unroll
        for (int i = 0; i < 2; i++) {
            int c = tid + i * 256;
            int r = c >> 2, kc = (c & 3) * 8;
            cp16(As + s * A_STAGE + r * AS_STRIDE + kc, Abase + (size_t)r * FF + k0 + kc);
        }
#pragma unroll
        for (int i = 0; i < 2; i++) {
            int c = tid + i * 256;
            int kr = c >> 4, nc = (c & 15) * 8;
            cp16(Bs + s * B_STAGE + kr * BS_STRIDE + nc, Bbase + (size_t)(k0 + kr) * DIM + nc);
        }
        cp_commit();
    };

    wmma::fragment<wmma::accumulator, 16, 16, 16, float> acc[2][4];
#pragma unroll
    for (int i = 0; i < 2; i++)
#pragma unroll
        for (int j = 0; j < 4; j++) wmma::fill_fragment(acc[i][j], 0.f);

    int warp = tid >> 5;
    int wm = warp >> 1;            // 0..3
    int wn = warp & 1;             // 0..1

    load_stage(0, 0);
    for (int it = 0; it < FF / 32; it++) {
        int s = it & 1;
        if (it + 1 < FF / 32) load_stage(s ^ 1, (it + 1) * 32);
        else cp_commit();
        cp_wait1();
        __syncthreads();

        const __nv_bfloat16* Ab = As + s * A_STAGE + (wm * 32) * AS_STRIDE;
        const __nv_bfloat16* Bb = Bs + s * B_STAGE + wn * 64;
#pragma unroll
        for (int kk = 0; kk < 32; kk += 16) {
            wmma::fragment<wmma::matrix_a, 16, 16, 16, __nv_bfloat16, wmma::row_major> af[2];
            wmma::fragment<wmma::matrix_b, 16, 16, 16, __nv_bfloat16, wmma::row_major> bf[4];
            wmma::load_matrix_sync(af[0], Ab + kk, AS_STRIDE);
            wmma::load_matrix_sync(af[1], Ab + 16 * AS_STRIDE + kk, AS_STRIDE);
#pragma unroll
            for (int j = 0; j < 4; j++)
                wmma::load_matrix_sync(bf[j], Bb + kk * BS_STRIDE + j * 16, BS_STRIDE);
#pragma unroll
            for (int i = 0; i < 2; i++)
#pragma unroll
                for (int j = 0; j < 4; j++)
                    wmma::mma_sync(acc[i][j], af[i], bf[j], acc[i][j]);
        }
        __syncthreads();
    }

    // epilogue: stage full 128x128 fp32 tile, then scaled scatter
    float* Cs = (float*)smem;
#pragma unroll
    for (int i = 0; i < 2; i++)
#pragma unroll
        for (int j = 0; j < 4; j++)
            wmma::store_matrix_sync(Cs + (wm * 32 + i * 16) * 128 + wn * 64 + j * 16,
                                    acc[i][j], 128, wmma::mem_row_major);
    __syncthreads();

    for (int idx = tid; idx < 128 * 128; idx += 256) {
        int r = idx >> 7, c = idx & 127;
        if (m0 + r < rows) {
            int tok = stok[r];
            g_ffn[(size_t)tok * DIM + n0 + c] = Cs[idx] * sprob[r];
        }
    }
}

// ---------------- residual + LayerNorm --------------------------------------
__global__ void __launch_bounds__(256) k_ln(const float* __restrict__ x,
                                            const float* __restrict__ lng,
                                            const float* __restrict__ lnb,
                                            float* __restrict__ out) {
    int t = blockIdx.x, tid = threadIdx.x;
    const float* xr = x + (size_t)t * DIM;
    const float* fr = g_ffn + (size_t)t * DIM;
    float v[4], s = 0.f, s2 = 0.f;
#pragma unroll
    for (int i = 0; i < 4; i++) {
        int c = tid + i * 256;
        float r = xr[c] + fr[c];
        v[i] = r; s += r; s2 += r * r;
    }
#pragma unroll
    for (int o = 16; o; o >>= 1) {
        s  += __shfl_xor_sync(0xffffffffu, s, o);
        s2 += __shfl_xor_sync(0xffffffffu, s2, o);
    }
    __shared__ float sh[16];
    int w = tid >> 5;
    if ((tid & 31) == 0) { sh[w] = s; sh[8 + w] = s2; }
    __syncthreads();
    float S = 0.f, S2 = 0.f;
#pragma unroll
    for (int i = 0; i < 8; i++) { S += sh[i]; S2 += sh[8 + i]; }
    float mu = S * (1.f / DIM);
    float var = S2 * (1.f / DIM) - mu * mu;
    float inv = rsqrtf(var + 1e-5f);
    float* orow = out + (size_t)t * DIM;
#pragma unroll
    for (int i = 0; i < 4; i++) {
        int c = tid + i * 256;
        orow[c] = (v[i] - mu) * inv * lng[c] + lnb[c];
    }
}

// ---------------- load-balance loss ------------------------------------------
__global__ void k_loss(float* __restrict__ out, int out_size) {
    if (threadIdx.x == 0 && blockIdx.x == 0) {
        float lb = 0.f;
        const float invN = 1.f / (float)NTOK;
#pragma unroll
        for (int e = 0; e < NE; e++)
            lb += ((float)g_cnt[e] * invN) * (g_sumP[e] * invN);
        lb *= (float)NE;
        if (out_size > NTOK * DIM) out[NTOK * DIM] = lb;
    }
}

// ---------------- launch ------------------------------------------------------
extern "C" void kernel_launch(void* const* d_in, const int* in_sizes, int n_in,
                              void* d_out, int out_size) {
    const float* x   = (const float*)d_in[0];
    const float* rw  = (const float*)d_in[1];
    const float* gw  = (const float*)d_in[2];
    const float* uw  = (const float*)d_in[3];
    const float* dw  = (const float*)d_in[4];
    const float* lng = (const float*)d_in[5];
    const float* lnb = (const float*)d_in[6];
    float* out = (float*)d_out;
    (void)in_sizes; (void)n_in;

    static bool attr_done = false;
    if (!attr_done) {
        cudaFuncSetAttribute(k_gemm1, cudaFuncAttributeMaxDynamicSharedMemorySize, 65536);
        cudaFuncSetAttribute(k_gemm2, cudaFuncAttributeMaxDynamicSharedMemorySize, 65536);
        attr_done = true;
    }

    k_init<<<1, 32>>>();
    k_convert<<<4096, 256>>>(x,  NTOK * DIM, 0);
    k_convert<<<8192, 256>>>(gw, NE * DIM * FF, 1);
    k_convert<<<8192, 256>>>(uw, NE * DIM * FF, 2);
    k_convert<<<8192, 256>>>(dw, NE * FF * DIM, 3);
    k_zero_ffn<<<4096, 256>>>();
    k_router<<<NTOK / 8, 256>>>(x, rw);
    k_scan<<<1, 256>>>();

    k_gemm1<<<dim3(NE * NBM1, FF / 128), 512, 65536>>>();
    k_gemm2<<<dim3(NE * NBM2, DIM / 128), 256, 65536>>>();

    k_ln<<<NTOK, 256>>>(x, lng, lnb, out);
    k_loss<<<1, 1>>>(out, out_size);
}

// round 5
// speedup vs baseline: 1.6274x; 1.4086x over previous
#include <cuda_runtime.h>
#include <cuda_bf16.h>
#include <cstdint>

#define NTOK 16384
#define DIM  1024
#define FF   4096
#define NE   8
#define CAP  2560
#define NBM  20            // CAP / 128
#define BK   64
#define NIT1 (DIM / BK)    // 16
#define NIT2 (FF / BK)     // 64
#define ST1  49152         // stage bytes gemm1: A 16K + Bg 16K + Bu 16K
#define ST2  32768         // stage bytes gemm2: A 16K + B 16K

// ---------------- scratch globals -------------------------------------------
__device__ __nv_bfloat16 g_xb[(size_t)NTOK * DIM];
__device__ __nv_bfloat16 g_wgT[(size_t)NE * FF * DIM];  // [E][F][D]
__device__ __nv_bfloat16 g_wuT[(size_t)NE * FF * DIM];  // [E][F][D]
__device__ __nv_bfloat16 g_wdT[(size_t)NE * DIM * FF];  // [E][D][F]
__device__ __nv_bfloat16 g_h[(size_t)NE * CAP * FF];
__device__ float g_ffn[(size_t)NTOK * DIM];
__device__ int   g_top1[NTOK];
__device__ float g_topv[NTOK];
__device__ int   g_dest[NE * CAP];
__device__ int   g_rows[NE];
__device__ int   g_cnt[NE];
__device__ float g_sumP[NE];

// ---------------- PTX helpers ------------------------------------------------
__device__ __forceinline__ uint32_t s2u(const void* p) {
    return (uint32_t)__cvta_generic_to_shared(p);
}
__device__ __forceinline__ void cp16(uint32_t dst, const void* src) {
    asm volatile("cp.async.cg.shared.global [%0], [%1], 16;\n" :: "r"(dst), "l"(src));
}
__device__ __forceinline__ void cp_commit() { asm volatile("cp.async.commit_group;\n" ::: "memory"); }
__device__ __forceinline__ void cp_wait0()  { asm volatile("cp.async.wait_group 0;\n" ::: "memory"); }
__device__ __forceinline__ void cp_wait1()  { asm volatile("cp.async.wait_group 1;\n" ::: "memory"); }

__device__ __forceinline__ void ldsm4(uint32_t (&d)[4], uint32_t addr) {
    asm volatile("ldmatrix.sync.aligned.m8n8.x4.shared.b16 {%0,%1,%2,%3}, [%4];"
        : "=r"(d[0]), "=r"(d[1]), "=r"(d[2]), "=r"(d[3]) : "r"(addr));
}
__device__ __forceinline__ void mma16816(float (&c)[4], const uint32_t (&a)[4],
                                         uint32_t b0, uint32_t b1) {
    asm volatile("mma.sync.aligned.m16n8k16.row.col.f32.bf16.bf16.f32 "
        "{%0,%1,%2,%3}, {%4,%5,%6,%7}, {%8,%9}, {%0,%1,%2,%3};"
        : "+f"(c[0]), "+f"(c[1]), "+f"(c[2]), "+f"(c[3])
        : "r"(a[0]), "r"(a[1]), "r"(a[2]), "r"(a[3]), "r"(b0), "r"(b1));
}

// ---------------- small kernels ---------------------------------------------
__global__ void k_init() {
    int t = threadIdx.x;
    if (t < NE) g_sumP[t] = 0.f;
}

__global__ void k_convert_x(const float* __restrict__ in) {
    int stride = gridDim.x * blockDim.x * 4;
    for (int i = (blockIdx.x * blockDim.x + threadIdx.x) * 4; i < NTOK * DIM; i += stride) {
        float4 v = *(const float4*)(in + i);
        *(__nv_bfloat162*)(g_xb + i)     = __floats2bfloat162_rn(v.x, v.y);
        *(__nv_bfloat162*)(g_xb + i + 2) = __floats2bfloat162_rn(v.z, v.w);
    }
}

// fp32 [E][R][C] -> bf16 [E][C][R]
__global__ void __launch_bounds__(256) k_transpose(const float* __restrict__ in,
                                                   __nv_bfloat16* __restrict__ out,
                                                   int R, int C) {
    __shared__ float tile[32][33];
    int e = blockIdx.z;
    int c0 = blockIdx.x * 32, r0 = blockIdx.y * 32;
    int tx = threadIdx.x & 31, ty = threadIdx.x >> 5;
    const float* src = in + (size_t)e * R * C;
    __nv_bfloat16* dst = out + (size_t)e * C * R;
#pragma unroll
    for (int k = 0; k < 4; k++)
        tile[ty + 8 * k][tx] = src[(size_t)(r0 + ty + 8 * k) * C + c0 + tx];
    __syncthreads();
#pragma unroll
    for (int k = 0; k < 4; k++)
        dst[(size_t)(c0 + ty + 8 * k) * R + r0 + tx] = __float2bfloat16(tile[tx][ty + 8 * k]);
}

__global__ void k_zero_ffn() {
    int stride = gridDim.x * blockDim.x * 4;
    float4 z = make_float4(0.f, 0.f, 0.f, 0.f);
    for (int i = (blockIdx.x * blockDim.x + threadIdx.x) * 4; i < NTOK * DIM; i += stride)
        *(float4*)(g_ffn + i) = z;
}

// ---------------- router ------------------------------------------------------
__global__ void __launch_bounds__(256) k_router(const float* __restrict__ x,
                                                const float* __restrict__ rw) {
    __shared__ float rws[DIM * NE];
    __shared__ float blockP[NE];
    int tid = threadIdx.x;
    for (int i = tid; i < DIM * NE; i += 256) rws[i] = rw[i];
    if (tid < NE) blockP[tid] = 0.f;
    __syncthreads();

    int warp = tid >> 5, lane = tid & 31;
    int token = blockIdx.x * 8 + warp;

    float acc[NE];
#pragma unroll
    for (int e = 0; e < NE; e++) acc[e] = 0.f;
    const float* xr = x + (size_t)token * DIM;
    for (int i = lane; i < DIM; i += 32) {
        float xv = xr[i];
#pragma unroll
        for (int e = 0; e < NE; e++) acc[e] += xv * rws[i * NE + e];
    }
#pragma unroll
    for (int e = 0; e < NE; e++)
#pragma unroll
        for (int o = 16; o; o >>= 1) acc[e] += __shfl_xor_sync(0xffffffffu, acc[e], o);

    if (lane == 0) {
        float m = acc[0]; int am = 0;
#pragma unroll
        for (int e = 1; e < NE; e++) if (acc[e] > m) { m = acc[e]; am = e; }
        float p[NE], s = 0.f;
#pragma unroll
        for (int e = 0; e < NE; e++) { p[e] = __expf(acc[e] - m); s += p[e]; }
        float inv = 1.f / s;
        g_top1[token] = am;
        g_topv[token] = p[am] * inv;
#pragma unroll
        for (int e = 0; e < NE; e++) atomicAdd(&blockP[e], p[e] * inv);
    }
    __syncthreads();
    if (tid < NE) atomicAdd(&g_sumP[tid], blockP[tid]);
}

// ---------------- deterministic token-order scan ------------------------------
__global__ void k_scan() {
    __shared__ int ids[256];
    __shared__ int base[NE];
    __shared__ int wc[NE];
    int tid = threadIdx.x;
    if (tid < NE) base[tid] = 0;
    __syncthreads();
    for (int w = 0; w < NTOK / 256; w++) {
        int t = w * 256 + tid;
        ids[tid] = g_top1[t];
        __syncthreads();
        int e = ids[tid];
        int r = 0;
        for (int j = 0; j < tid; j++) r += (ids[j] == e);
        if (tid < NE) {
            int c = 0;
            for (int j = 0; j < 256; j++) c += (ids[j] == tid);
            wc[tid] = c;
        }
        int p = base[e] + r;
        if (p < CAP) g_dest[e * CAP + p] = t;
        __syncthreads();
        if (tid < NE) base[tid] += wc[tid];
        __syncthreads();
    }
    if (tid < NE) {
        g_cnt[tid] = base[tid];
        g_rows[tid] = min(base[tid], CAP);
    }
}

// ---------------- GEMM1: mma.sync, h = silu(X Wg) * (X Wu) -------------------
// CTA: M=128 x N=128 (both gate and up), K-step 64; 512 threads.
// warps 0-7 gate, 8-15 up; warp tile 64x32 (2m x 4n layout).
__global__ void __launch_bounds__(512, 1) k_gemm1() {
    extern __shared__ char smem[];
    __shared__ const __nv_bfloat16* tokp[128];

    int e = blockIdx.x / NBM;
    int m0 = (blockIdx.x % NBM) * 128;
    int rows = g_rows[e];
    if (m0 >= rows) return;
    int n0 = blockIdx.y * 128;
    int tid = threadIdx.x;
    int wid = tid >> 5, l = tid & 31;

    if (tid < 128) {
        int gr = m0 + tid;
        tokp[tid] = g_xb + (size_t)g_dest[e * CAP + ((gr < rows) ? gr : 0)] * DIM;
    }
    __syncthreads();

    uint32_t sb = s2u(smem);
    const __nv_bfloat16* gB = g_wgT + (size_t)e * FF * DIM + (size_t)n0 * DIM;
    const __nv_bfloat16* uB = g_wuT + (size_t)e * FF * DIM + (size_t)n0 * DIM;

    auto load_stage = [&](int s, int kb) {
        int k0 = kb * BK;
        uint32_t st = sb + s * ST1;
#pragma unroll
        for (int i = 0; i < 2; i++) {
            int idx = tid + i * 512;
            int r = idx >> 3, c = idx & 7;
            uint32_t o = r * 128 + ((c ^ (r & 7)) << 4);
            cp16(st + o, tokp[r] + k0 + c * 8);
            cp16(st + 16384 + o, gB + (size_t)r * DIM + k0 + c * 8);
            cp16(st + 32768 + o, uB + (size_t)r * DIM + k0 + c * 8);
        }
        cp_commit();
    };

    int mat = wid >> 3;          // 0 = gate, 1 = up
    int w   = wid & 7;
    int wm  = w >> 2;            // 0..1
    int wn  = w & 3;             // 0..3
    int grow = ((l >> 3) & 1) * 8 + (l & 7);
    int gk   = l >> 4;
    int rsw  = grow & 7;
    uint32_t rowA[4], rowB[2];
#pragma unroll
    for (int i = 0; i < 4; i++) rowA[i] = (wm * 64 + i * 16 + grow) * 128;
#pragma unroll
    for (int nf = 0; nf < 2; nf++)
        rowB[nf] = 16384 + mat * 16384 + (wn * 32 + nf * 16 + grow) * 128;

    float acc[4][4][4];
#pragma unroll
    for (int i = 0; i < 4; i++)
#pragma unroll
        for (int j = 0; j < 4; j++)
#pragma unroll
            for (int k = 0; k < 4; k++) acc[i][j][k] = 0.f;

    load_stage(0, 0);
    load_stage(1, 1);

    for (int it = 0; it < NIT1; it++) {
        int s = it % 3;
        if (it < NIT1 - 1) cp_wait1(); else cp_wait0();
        __syncthreads();
        if (it + 2 < NIT1) load_stage((it + 2) % 3, it + 2);
        uint32_t st = sb + s * ST1;
#pragma unroll
        for (int kk = 0; kk < 4; kk++) {
            int ck = kk * 2 + gk;
            uint32_t koff = (uint32_t)((ck ^ rsw) << 4);
            uint32_t a[4][4], bb[2][4];
#pragma unroll
            for (int i = 0; i < 4; i++) ldsm4(a[i], st + rowA[i] + koff);
#pragma unroll
            for (int nf = 0; nf < 2; nf++) ldsm4(bb[nf], st + rowB[nf] + koff);
#pragma unroll
            for (int i = 0; i < 4; i++) {
                mma16816(acc[i][0], a[i], bb[0][0], bb[0][2]);
                mma16816(acc[i][1], a[i], bb[0][1], bb[0][3]);
                mma16816(acc[i][2], a[i], bb[1][0], bb[1][2]);
                mma16816(acc[i][3], a[i], bb[1][1], bb[1][3]);
            }
        }
    }
    __syncthreads();

    // epilogue: up warps stage fp32 to smem; gate warps combine + write global
    float* Cu = (float*)smem;     // 128 x 136 fp32
    if (mat == 1) {
#pragma unroll
        for (int i = 0; i < 4; i++)
#pragma unroll
            for (int j = 0; j < 4; j++) {
                int r = wm * 64 + i * 16 + (l >> 2);
                int c = wn * 32 + j * 8 + (l & 3) * 2;
                Cu[r * 136 + c]           = acc[i][j][0];
                Cu[r * 136 + c + 1]       = acc[i][j][1];
                Cu[(r + 8) * 136 + c]     = acc[i][j][2];
                Cu[(r + 8) * 136 + c + 1] = acc[i][j][3];
            }
    }
    __syncthreads();
    if (mat == 0) {
#pragma unroll
        for (int i = 0; i < 4; i++)
#pragma unroll
            for (int j = 0; j < 4; j++) {
                int r = wm * 64 + i * 16 + (l >> 2);
                int c = wn * 32 + j * 8 + (l & 3) * 2;
#pragma unroll
                for (int h = 0; h < 2; h++) {
                    int rr = r + h * 8;
                    if (m0 + rr < rows) {
                        float g0 = acc[i][j][2 * h], g1 = acc[i][j][2 * h + 1];
                        float u0 = Cu[rr * 136 + c], u1 = Cu[rr * 136 + c + 1];
                        float h0 = g0 / (1.f + __expf(-g0)) * u0;
                        float h1 = g1 / (1.f + __expf(-g1)) * u1;
                        __nv_bfloat162 b2 = __floats2bfloat162_rn(h0, h1);
                        *(uint32_t*)(g_h + ((size_t)e * CAP + m0 + rr) * FF + n0 + c) =
                            *(uint32_t*)&b2;
                    }
                }
            }
    }
}

// ---------------- GEMM2: mma.sync, y = H Wd, scaled scatter -------------------
// CTA: M=128 x N=128, K-step 64; 256 threads; warps 2m x 4n of 64x32.
__global__ void __launch_bounds__(256, 2) k_gemm2() {
    extern __shared__ char smem[];
    __shared__ int   stok[128];
    __shared__ float sprob[128];

    int e = blockIdx.x / NBM;
    int m0 = (blockIdx.x % NBM) * 128;
    int rows = g_rows[e];
    if (m0 >= rows) return;
    int n0 = blockIdx.y * 128;
    int tid = threadIdx.x;
    int wid = tid >> 5, l = tid & 31;

    if (tid < 128) {
        int gr = m0 + tid;
        int tok = g_dest[e * CAP + ((gr < rows) ? gr : 0)];
        stok[tid] = tok;
        sprob[tid] = g_topv[tok];
    }
    __syncthreads();

    uint32_t sb = s2u(smem);
    const __nv_bfloat16* Ab = g_h + ((size_t)e * CAP + m0) * FF;
    const __nv_bfloat16* Bb = g_wdT + (size_t)e * DIM * FF + (size_t)n0 * FF;

    auto load_stage = [&](int s, int kb) {
        int k0 = kb * BK;
        uint32_t st = sb + s * ST2;
#pragma unroll
        for (int i = 0; i < 4; i++) {
            int idx = tid + i * 256;
            int r = idx >> 3, c = idx & 7;
            uint32_t o = r * 128 + ((c ^ (r & 7)) << 4);
            cp16(st + o, Ab + (size_t)r * FF + k0 + c * 8);
            cp16(st + 16384 + o, Bb + (size_t)r * FF + k0 + c * 8);
        }
        cp_commit();
    };

    int wm = wid >> 2;           // 0..1
    int wn = wid & 3;            // 0..3
    int grow = ((l >> 3) & 1) * 8 + (l & 7);
    int gk   = l >> 4;
    int rsw  = grow & 7;
    uint32_t rowA[4], rowB[2];
#pragma unroll
    for (int i = 0; i < 4; i++) rowA[i] = (wm * 64 + i * 16 + grow) * 128;
#pragma unroll
    for (int nf = 0; nf < 2; nf++)
        rowB[nf] = 16384 + (wn * 32 + nf * 16 + grow) * 128;

    float acc[4][4][4];
#pragma unroll
    for (int i = 0; i < 4; i++)
#pragma unroll
        for (int j = 0; j < 4; j++)
#pragma unroll
            for (int k = 0; k < 4; k++) acc[i][j][k] = 0.f;

    load_stage(0, 0);
    load_stage(1, 1);

    for (int it = 0; it < NIT2; it++) {
        int s = it % 3;
        if (it < NIT2 - 1) cp_wait1(); else cp_wait0();
        __syncthreads();
        if (it + 2 < NIT2) load_stage((it + 2) % 3, it + 2);
        uint32_t st = sb + s * ST2;
#pragma unroll
        for (int kk = 0; kk < 4; kk++) {
            int ck = kk * 2 + gk;
            uint32_t koff = (uint32_t)((ck ^ rsw) << 4);
            uint32_t a[4][4], bb[2][4];
#pragma unroll
            for (int i = 0; i < 4; i++) ldsm4(a[i], st + rowA[i] + koff);
#pragma unroll
            for (int nf = 0; nf < 2; nf++) ldsm4(bb[nf], st + rowB[nf] + koff);
#pragma unroll
            for (int i = 0; i < 4; i++) {
                mma16816(acc[i][0], a[i], bb[0][0], bb[0][2]);
                mma16816(acc[i][1], a[i], bb[0][1], bb[0][3]);
                mma16816(acc[i][2], a[i], bb[1][0], bb[1][2]);
                mma16816(acc[i][3], a[i], bb[1][1], bb[1][3]);
            }
        }
    }
    __syncthreads();

    // stage fp32 result, then coalesced scaled scatter
    float* Cs = (float*)smem;     // 128 x 136 fp32
#pragma unroll
    for (int i = 0; i < 4; i++)
#pragma unroll
        for (int j = 0; j < 4; j++) {
            int r = wm * 64 + i * 16 + (l >> 2);
            int c = wn * 32 + j * 8 + (l & 3) * 2;
            Cs[r * 136 + c]           = acc[i][j][0];
            Cs[r * 136 + c + 1]       = acc[i][j][1];
            Cs[(r + 8) * 136 + c]     = acc[i][j][2];
            Cs[(r + 8) * 136 + c + 1] = acc[i][j][3];
        }
    __syncthreads();

#pragma unroll
    for (int k = 0; k < 16; k++) {
        int idx = tid + k * 256;
        int r = idx >> 5, cc = (idx & 31) * 4;
        if (m0 + r < rows) {
            int tok = stok[r];
            float p = sprob[r];
            float4 v;
            v.x = Cs[r * 136 + cc]     * p;
            v.y = Cs[r * 136 + cc + 1] * p;
            v.z = Cs[r * 136 + cc + 2] * p;
            v.w = Cs[r * 136 + cc + 3] * p;
            *(float4*)(g_ffn + (size_t)tok * DIM + n0 + cc) = v;
        }
    }
}

// ---------------- residual + LayerNorm ----------------------------------------
__global__ void __launch_bounds__(256) k_ln(const float* __restrict__ x,
                                            const float* __restrict__ lng,
                                            const float* __restrict__ lnb,
                                            float* __restrict__ out) {
    int t = blockIdx.x, tid = threadIdx.x;
    const float* xr = x + (size_t)t * DIM;
    const float* fr = g_ffn + (size_t)t * DIM;
    float v[4], s = 0.f, s2 = 0.f;
#pragma unroll
    for (int i = 0; i < 4; i++) {
        int c = tid + i * 256;
        float r = xr[c] + fr[c];
        v[i] = r; s += r; s2 += r * r;
    }
#pragma unroll
    for (int o = 16; o; o >>= 1) {
        s  += __shfl_xor_sync(0xffffffffu, s, o);
        s2 += __shfl_xor_sync(0xffffffffu, s2, o);
    }
    __shared__ float sh[16];
    int w = tid >> 5;
    if ((tid & 31) == 0) { sh[w] = s; sh[8 + w] = s2; }
    __syncthreads();
    float S = 0.f, S2 = 0.f;
#pragma unroll
    for (int i = 0; i < 8; i++) { S += sh[i]; S2 += sh[8 + i]; }
    float mu = S * (1.f / DIM);
    float var = S2 * (1.f / DIM) - mu * mu;
    float inv = rsqrtf(var + 1e-5f);
    float* orow = out + (size_t)t * DIM;
#pragma unroll
    for (int i = 0; i < 4; i++) {
        int c = tid + i * 256;
        orow[c] = (v[i] - mu) * inv * lng[c] + lnb[c];
    }
}

// ---------------- load-balance loss --------------------------------------------
__global__ void k_loss(float* __restrict__ out, int out_size) {
    if (threadIdx.x == 0 && blockIdx.x == 0) {
        float lb = 0.f;
        const float invN = 1.f / (float)NTOK;
#pragma unroll
        for (int e = 0; e < NE; e++)
            lb += ((float)g_cnt[e] * invN) * (g_sumP[e] * invN);
        lb *= (float)NE;
        if (out_size > NTOK * DIM) out[NTOK * DIM] = lb;
    }
}

// ---------------- launch --------------------------------------------------------
extern "C" void kernel_launch(void* const* d_in, const int* in_sizes, int n_in,
                              void* d_out, int out_size) {
    const float* x   = (const float*)d_in[0];
    const float* rw  = (const float*)d_in[1];
    const float* gw  = (const float*)d_in[2];
    const float* uw  = (const float*)d_in[3];
    const float* dw  = (const float*)d_in[4];
    const float* lng = (const float*)d_in[5];
    const float* lnb = (const float*)d_in[6];
    float* out = (float*)d_out;
    (void)in_sizes; (void)n_in;

    static bool attr_done = false;
    if (!attr_done) {
        cudaFuncSetAttribute(k_gemm1, cudaFuncAttributeMaxDynamicSharedMemorySize, 3 * ST1);
        cudaFuncSetAttribute(k_gemm2, cudaFuncAttributeMaxDynamicSharedMemorySize, 3 * ST2);
        attr_done = true;
    }

    __nv_bfloat16* wgT; cudaGetSymbolAddress((void**)&wgT, g_wgT);
    __nv_bfloat16* wuT; cudaGetSymbolAddress((void**)&wuT, g_wuT);
    __nv_bfloat16* wdT; cudaGetSymbolAddress((void**)&wdT, g_wdT);

    k_init<<<1, 32>>>();
    k_convert_x<<<4096, 256>>>(x);
    k_transpose<<<dim3(FF / 32, DIM / 32, NE), 256>>>(gw, wgT, DIM, FF);
    k_transpose<<<dim3(FF / 32, DIM / 32, NE), 256>>>(uw, wuT, DIM, FF);
    k_transpose<<<dim3(DIM / 32, FF / 32, NE), 256>>>(dw, wdT, FF, DIM);
    k_zero_ffn<<<4096, 256>>>();
    k_router<<<NTOK / 8, 256>>>(x, rw);
    k_scan<<<1, 256>>>();

    k_gemm1<<<dim3(NE * NBM, FF / 128), 512, 3 * ST1>>>();
    k_gemm2<<<dim3(NE * NBM, DIM / 128), 256, 3 * ST2>>>();

    k_ln<<<NTOK, 256>>>(x, lng, lnb, out);
    k_loss<<<1, 1>>>(out, out_size);
}

// round 6
// speedup vs baseline: 1.6641x; 1.0226x over previous
#include <cuda_runtime.h>
#include <cuda_bf16.h>
#include <cstdint>

#define NTOK 16384
#define DIM  1024
#define FF   4096
#define NE   8
#define CAP  2560
#define NBM  20            // CAP / 128
#define BK   64
#define NIT1 (DIM / BK)    // 16
#define NIT2 (FF / BK)     // 64
#define ST1  49152         // stage bytes gemm1: A 16K + Bg 16K + Bu 16K
#define ST2  32768         // stage bytes gemm2: A 16K + B 16K

// ---------------- scratch globals -------------------------------------------
__device__ __nv_bfloat16 g_xb[(size_t)NTOK * DIM];
__device__ __nv_bfloat16 g_wgT[(size_t)NE * FF * DIM];  // [E][F][D]
__device__ __nv_bfloat16 g_wuT[(size_t)NE * FF * DIM];  // [E][F][D]
__device__ __nv_bfloat16 g_wdT[(size_t)NE * DIM * FF];  // [E][D][F]
__device__ __nv_bfloat16 g_h[(size_t)NE * CAP * FF];
__device__ float g_ffn[(size_t)NTOK * DIM];
__device__ int   g_top1[NTOK];
__device__ float g_topv[NTOK];
__device__ int   g_dest[NE * CAP];
__device__ int   g_rows[NE];
__device__ int   g_cnt[NE];
__device__ float g_sumP[NE];

// ---------------- PTX helpers ------------------------------------------------
__device__ __forceinline__ uint32_t s2u(const void* p) {
    return (uint32_t)__cvta_generic_to_shared(p);
}
__device__ __forceinline__ void cp16(uint32_t dst, const void* src) {
    asm volatile("cp.async.cg.shared.global [%0], [%1], 16;\n" :: "r"(dst), "l"(src));
}
__device__ __forceinline__ void cp_commit() { asm volatile("cp.async.commit_group;\n" ::: "memory"); }
__device__ __forceinline__ void cp_wait0()  { asm volatile("cp.async.wait_group 0;\n" ::: "memory"); }
__device__ __forceinline__ void cp_wait1()  { asm volatile("cp.async.wait_group 1;\n" ::: "memory"); }

__device__ __forceinline__ void ldsm4(uint32_t (&d)[4], uint32_t addr) {
    asm volatile("ldmatrix.sync.aligned.m8n8.x4.shared.b16 {%0,%1,%2,%3}, [%4];"
        : "=r"(d[0]), "=r"(d[1]), "=r"(d[2]), "=r"(d[3]) : "r"(addr));
}
__device__ __forceinline__ void mma16816(float (&c)[4], const uint32_t (&a)[4],
                                         uint32_t b0, uint32_t b1) {
    asm volatile("mma.sync.aligned.m16n8k16.row.col.f32.bf16.bf16.f32 "
        "{%0,%1,%2,%3}, {%4,%5,%6,%7}, {%8,%9}, {%0,%1,%2,%3};"
        : "+f"(c[0]), "+f"(c[1]), "+f"(c[2]), "+f"(c[3])
        : "r"(a[0]), "r"(a[1]), "r"(a[2]), "r"(a[3]), "r"(b0), "r"(b1));
}

// ---------------- small kernels ---------------------------------------------
__global__ void k_init() {
    int t = threadIdx.x;
    if (t < NE) g_sumP[t] = 0.f;
}

// fp32 [E][R][C] -> bf16 [E][C][R]
__global__ void __launch_bounds__(256) k_transpose(const float* __restrict__ in,
                                                   __nv_bfloat16* __restrict__ out,
                                                   int R, int C) {
    __shared__ float tile[32][33];
    int e = blockIdx.z;
    int c0 = blockIdx.x * 32, r0 = blockIdx.y * 32;
    int tx = threadIdx.x & 31, ty = threadIdx.x >> 5;
    const float* src = in + (size_t)e * R * C;
    __nv_bfloat16* dst = out + (size_t)e * C * R;
#pragma unroll
    for (int k = 0; k < 4; k++)
        tile[ty + 8 * k][tx] = src[(size_t)(r0 + ty + 8 * k) * C + c0 + tx];
    __syncthreads();
#pragma unroll
    for (int k = 0; k < 4; k++)
        dst[(size_t)(c0 + ty + 8 * k) * R + r0 + tx] = __float2bfloat16(tile[tx][ty + 8 * k]);
}

__global__ void k_zero_ffn() {
    int stride = gridDim.x * blockDim.x * 4;
    float4 z = make_float4(0.f, 0.f, 0.f, 0.f);
    for (int i = (blockIdx.x * blockDim.x + threadIdx.x) * 4; i < NTOK * DIM; i += stride)
        *(float4*)(g_ffn + i) = z;
}

// ---------------- router (also converts x -> bf16) ---------------------------
__global__ void __launch_bounds__(256) k_router(const float* __restrict__ x,
                                                const float* __restrict__ rw) {
    __shared__ float rws[DIM * NE];
    __shared__ float blockP[NE];
    int tid = threadIdx.x;
    for (int i = tid; i < DIM * NE; i += 256) rws[i] = rw[i];
    if (tid < NE) blockP[tid] = 0.f;
    __syncthreads();

    int warp = tid >> 5, lane = tid & 31;
    int token = blockIdx.x * 8 + warp;

    float acc[NE];
#pragma unroll
    for (int e = 0; e < NE; e++) acc[e] = 0.f;
    const float* xr = x + (size_t)token * DIM;
    __nv_bfloat16* xb = g_xb + (size_t)token * DIM;
    for (int i = lane * 4; i < DIM; i += 128) {
        float4 v = *(const float4*)(xr + i);
        *(__nv_bfloat162*)(xb + i)     = __floats2bfloat162_rn(v.x, v.y);
        *(__nv_bfloat162*)(xb + i + 2) = __floats2bfloat162_rn(v.z, v.w);
#pragma unroll
        for (int e = 0; e < NE; e++) {
            acc[e] += v.x * rws[i * NE + e];
            acc[e] += v.y * rws[(i + 1) * NE + e];
            acc[e] += v.z * rws[(i + 2) * NE + e];
            acc[e] += v.w * rws[(i + 3) * NE + e];
        }
    }
#pragma unroll
    for (int e = 0; e < NE; e++)
#pragma unroll
        for (int o = 16; o; o >>= 1) acc[e] += __shfl_xor_sync(0xffffffffu, acc[e], o);

    if (lane == 0) {
        float m = acc[0]; int am = 0;
#pragma unroll
        for (int e = 1; e < NE; e++) if (acc[e] > m) { m = acc[e]; am = e; }
        float p[NE], s = 0.f;
#pragma unroll
        for (int e = 0; e < NE; e++) { p[e] = __expf(acc[e] - m); s += p[e]; }
        float inv = 1.f / s;
        g_top1[token] = am;
        g_topv[token] = p[am] * inv;
#pragma unroll
        for (int e = 0; e < NE; e++) atomicAdd(&blockP[e], p[e] * inv);
    }
    __syncthreads();
    if (tid < NE) atomicAdd(&g_sumP[tid], blockP[tid]);
}

// ---------------- deterministic token-order scan (ballot version) ------------
__global__ void k_scan() {
    __shared__ int base[NE];
    __shared__ int wcnt[8][NE];
    int tid = threadIdx.x;
    int warp = tid >> 5, lane = tid & 31;
    unsigned ltmask = (1u << lane) - 1u;
    if (tid < NE) base[tid] = 0;
    __syncthreads();
    for (int w = 0; w < NTOK / 256; w++) {
        int t = w * 256 + tid;
        int e = g_top1[t];
        int myrank = 0;
#pragma unroll
        for (int ee = 0; ee < NE; ee++) {
            unsigned b = __ballot_sync(0xffffffffu, e == ee);
            if (lane == ee) wcnt[warp][ee] = __popc(b);
            if (e == ee) myrank = __popc(b & ltmask);
        }
        __syncthreads();
        int off = base[e];
        for (int w2 = 0; w2 < warp; w2++) off += wcnt[w2][e];
        int p = off + myrank;
        if (p < CAP) g_dest[e * CAP + p] = t;
        __syncthreads();
        if (tid < NE) {
            int s = 0;
#pragma unroll
            for (int w2 = 0; w2 < 8; w2++) s += wcnt[w2][tid];
            base[tid] += s;
        }
        __syncthreads();
    }
    if (tid < NE) {
        g_cnt[tid] = base[tid];
        g_rows[tid] = min(base[tid], CAP);
    }
}

// ---------------- GEMM1: mma.sync, h = silu(X Wg) * (X Wu) -------------------
__global__ void __launch_bounds__(512, 1) k_gemm1() {
    extern __shared__ char smem[];
    __shared__ const __nv_bfloat16* tokp[128];

    int e = blockIdx.x / NBM;
    int m0 = (blockIdx.x % NBM) * 128;
    int rows = g_rows[e];
    if (m0 >= rows) return;
    int n0 = blockIdx.y * 128;
    int tid = threadIdx.x;
    int wid = tid >> 5, l = tid & 31;

    if (tid < 128) {
        int gr = m0 + tid;
        tokp[tid] = g_xb + (size_t)g_dest[e * CAP + ((gr < rows) ? gr : 0)] * DIM;
    }
    __syncthreads();

    uint32_t sb = s2u(smem);
    const __nv_bfloat16* gB = g_wgT + (size_t)e * FF * DIM + (size_t)n0 * DIM;
    const __nv_bfloat16* uB = g_wuT + (size_t)e * FF * DIM + (size_t)n0 * DIM;

    auto load_stage = [&](int s, int kb) {
        int k0 = kb * BK;
        uint32_t st = sb + s * ST1;
#pragma unroll
        for (int i = 0; i < 2; i++) {
            int idx = tid + i * 512;
            int r = idx >> 3, c = idx & 7;
            uint32_t o = r * 128 + ((c ^ (r & 7)) << 4);
            cp16(st + o, tokp[r] + k0 + c * 8);
            cp16(st + 16384 + o, gB + (size_t)r * DIM + k0 + c * 8);
            cp16(st + 32768 + o, uB + (size_t)r * DIM + k0 + c * 8);
        }
        cp_commit();
    };

    int mat = wid >> 3;          // 0 = gate, 1 = up
    int w   = wid & 7;
    int wm  = w >> 2;            // 0..1
    int wn  = w & 3;             // 0..3
    int grow = ((l >> 3) & 1) * 8 + (l & 7);
    int gk   = l >> 4;
    int rsw  = grow & 7;
    uint32_t rowA[4], rowB[2];
#pragma unroll
    for (int i = 0; i < 4; i++) rowA[i] = (wm * 64 + i * 16 + grow) * 128;
#pragma unroll
    for (int nf = 0; nf < 2; nf++)
        rowB[nf] = 16384 + mat * 16384 + (wn * 32 + nf * 16 + grow) * 128;

    float acc[4][4][4];
#pragma unroll
    for (int i = 0; i < 4; i++)
#pragma unroll
        for (int j = 0; j < 4; j++)
#pragma unroll
            for (int k = 0; k < 4; k++) acc[i][j][k] = 0.f;

    load_stage(0, 0);
    load_stage(1, 1);

    for (int it = 0; it < NIT1; it++) {
        int s = it % 3;
        if (it < NIT1 - 1) cp_wait1(); else cp_wait0();
        __syncthreads();
        if (it + 2 < NIT1) load_stage((it + 2) % 3, it + 2);
        uint32_t st = sb + s * ST1;
#pragma unroll
        for (int kk = 0; kk < 4; kk++) {
            int ck = kk * 2 + gk;
            uint32_t koff = (uint32_t)((ck ^ rsw) << 4);
            uint32_t a[4][4], bb[2][4];
#pragma unroll
            for (int i = 0; i < 4; i++) ldsm4(a[i], st + rowA[i] + koff);
#pragma unroll
            for (int nf = 0; nf < 2; nf++) ldsm4(bb[nf], st + rowB[nf] + koff);
#pragma unroll
            for (int i = 0; i < 4; i++) {
                mma16816(acc[i][0], a[i], bb[0][0], bb[0][2]);
                mma16816(acc[i][1], a[i], bb[0][1], bb[0][3]);
                mma16816(acc[i][2], a[i], bb[1][0], bb[1][2]);
                mma16816(acc[i][3], a[i], bb[1][1], bb[1][3]);
            }
        }
    }
    __syncthreads();

    // epilogue: up warps stage fp32 to smem; gate warps compute silu*up into
    // a bf16 smem buffer; then all 512 threads stream uint4 stores to gmem.
    float* Cu = (float*)smem;                              // 128 x 136 fp32 (69.6KB)
    __nv_bfloat16* Hs = (__nv_bfloat16*)(smem + 73728);    // 128 x 136 bf16 (34.8KB)
    if (mat == 1) {
#pragma unroll
        for (int i = 0; i < 4; i++)
#pragma unroll
            for (int j = 0; j < 4; j++) {
                int r = wm * 64 + i * 16 + (l >> 2);
                int c = wn * 32 + j * 8 + (l & 3) * 2;
                Cu[r * 136 + c]           = acc[i][j][0];
                Cu[r * 136 + c + 1]       = acc[i][j][1];
                Cu[(r + 8) * 136 + c]     = acc[i][j][2];
                Cu[(r + 8) * 136 + c + 1] = acc[i][j][3];
            }
    }
    __syncthreads();
    if (mat == 0) {
#pragma unroll
        for (int i = 0; i < 4; i++)
#pragma unroll
            for (int j = 0; j < 4; j++) {
                int r = wm * 64 + i * 16 + (l >> 2);
                int c = wn * 32 + j * 8 + (l & 3) * 2;
#pragma unroll
                for (int h = 0; h < 2; h++) {
                    int rr = r + h * 8;
                    float g0 = acc[i][j][2 * h], g1 = acc[i][j][2 * h + 1];
                    float u0 = Cu[rr * 136 + c], u1 = Cu[rr * 136 + c + 1];
                    float h0 = g0 / (1.f + __expf(-g0)) * u0;
                    float h1 = g1 / (1.f + __expf(-g1)) * u1;
                    __nv_bfloat162 b2 = __floats2bfloat162_rn(h0, h1);
                    *(uint32_t*)(Hs + rr * 136 + c) = *(uint32_t*)&b2;
                }
            }
    }
    __syncthreads();
#pragma unroll
    for (int k = 0; k < 4; k++) {
        int idx = tid + k * 512;
        int r = idx >> 4, c8 = (idx & 15) * 8;
        if (m0 + r < rows)
            *(uint4*)(g_h + ((size_t)e * CAP + m0 + r) * FF + n0 + c8) =
                *(const uint4*)(Hs + r * 136 + c8);
    }
}

// ---------------- GEMM2: mma.sync, y = H Wd, scaled scatter -------------------
__global__ void __launch_bounds__(256, 2) k_gemm2() {
    extern __shared__ char smem[];
    __shared__ int   stok[128];
    __shared__ float sprob[128];

    int e = blockIdx.x / NBM;
    int m0 = (blockIdx.x % NBM) * 128;
    int rows = g_rows[e];
    if (m0 >= rows) return;
    int n0 = blockIdx.y * 128;
    int tid = threadIdx.x;
    int wid = tid >> 5, l = tid & 31;

    if (tid < 128) {
        int gr = m0 + tid;
        int tok = g_dest[e * CAP + ((gr < rows) ? gr : 0)];
        stok[tid] = tok;
        sprob[tid] = g_topv[tok];
    }
    __syncthreads();

    uint32_t sb = s2u(smem);
    const __nv_bfloat16* Ab = g_h + ((size_t)e * CAP + m0) * FF;
    const __nv_bfloat16* Bb = g_wdT + (size_t)e * DIM * FF + (size_t)n0 * FF;

    auto load_stage = [&](int s, int kb) {
        int k0 = kb * BK;
        uint32_t st = sb + s * ST2;
#pragma unroll
        for (int i = 0; i < 4; i++) {
            int idx = tid + i * 256;
            int r = idx >> 3, c = idx & 7;
            uint32_t o = r * 128 + ((c ^ (r & 7)) << 4);
            cp16(st + o, Ab + (size_t)r * FF + k0 + c * 8);
            cp16(st + 16384 + o, Bb + (size_t)r * FF + k0 + c * 8);
        }
        cp_commit();
    };

    int wm = wid >> 2;           // 0..1
    int wn = wid & 3;            // 0..3
    int grow = ((l >> 3) & 1) * 8 + (l & 7);
    int gk   = l >> 4;
    int rsw  = grow & 7;
    uint32_t rowA[4], rowB[2];
#pragma unroll
    for (int i = 0; i < 4; i++) rowA[i] = (wm * 64 + i * 16 + grow) * 128;
#pragma unroll
    for (int nf = 0; nf < 2; nf++)
        rowB[nf] = 16384 + (wn * 32 + nf * 16 + grow) * 128;

    float acc[4][4][4];
#pragma unroll
    for (int i = 0; i < 4; i++)
#pragma unroll
        for (int j = 0; j < 4; j++)
#pragma unroll
            for (int k = 0; k < 4; k++) acc[i][j][k] = 0.f;

    load_stage(0, 0);
    load_stage(1, 1);

    for (int it = 0; it < NIT2; it++) {
        int s = it % 3;
        if (it < NIT2 - 1) cp_wait1(); else cp_wait0();
        __syncthreads();
        if (it + 2 < NIT2) load_stage((it + 2) % 3, it + 2);
        uint32_t st = sb + s * ST2;
#pragma unroll
        for (int kk = 0; kk < 4; kk++) {
            int ck = kk * 2 + gk;
            uint32_t koff = (uint32_t)((ck ^ rsw) << 4);
            uint32_t a[4][4], bb[2][4];
#pragma unroll
            for (int i = 0; i < 4; i++) ldsm4(a[i], st + rowA[i] + koff);
#pragma unroll
            for (int nf = 0; nf < 2; nf++) ldsm4(bb[nf], st + rowB[nf] + koff);
#pragma unroll
            for (int i = 0; i < 4; i++) {
                mma16816(acc[i][0], a[i], bb[0][0], bb[0][2]);
                mma16816(acc[i][1], a[i], bb[0][1], bb[0][3]);
                mma16816(acc[i][2], a[i], bb[1][0], bb[1][2]);
                mma16816(acc[i][3], a[i], bb[1][1], bb[1][3]);
            }
        }
    }
    __syncthreads();

    // stage fp32 result, then coalesced scaled scatter
    float* Cs = (float*)smem;     // 128 x 136 fp32
#pragma unroll
    for (int i = 0; i < 4; i++)
#pragma unroll
        for (int j = 0; j < 4; j++) {
            int r = wm * 64 + i * 16 + (l >> 2);
            int c = wn * 32 + j * 8 + (l & 3) * 2;
            Cs[r * 136 + c]           = acc[i][j][0];
            Cs[r * 136 + c + 1]       = acc[i][j][1];
            Cs[(r + 8) * 136 + c]     = acc[i][j][2];
            Cs[(r + 8) * 136 + c + 1] = acc[i][j][3];
        }
    __syncthreads();

#pragma unroll
    for (int k = 0; k < 16; k++) {
        int idx = tid + k * 256;
        int r = idx >> 5, cc = (idx & 31) * 4;
        if (m0 + r < rows) {
            int tok = stok[r];
            float p = sprob[r];
            float4 v;
            v.x = Cs[r * 136 + cc]     * p;
            v.y = Cs[r * 136 + cc + 1] * p;
            v.z = Cs[r * 136 + cc + 2] * p;
            v.w = Cs[r * 136 + cc + 3] * p;
            *(float4*)(g_ffn + (size_t)tok * DIM + n0 + cc) = v;
        }
    }
}

// ---------------- residual + LayerNorm ----------------------------------------
__global__ void __launch_bounds__(256) k_ln(const float* __restrict__ x,
                                            const float* __restrict__ lng,
                                            const float* __restrict__ lnb,
                                            float* __restrict__ out) {
    int t = blockIdx.x, tid = threadIdx.x;
    const float* xr = x + (size_t)t * DIM;
    const float* fr = g_ffn + (size_t)t * DIM;
    float v[4], s = 0.f, s2 = 0.f;
#pragma unroll
    for (int i = 0; i < 4; i++) {
        int c = tid + i * 256;
        float r = xr[c] + fr[c];
        v[i] = r; s += r; s2 += r * r;
    }
#pragma unroll
    for (int o = 16; o; o >>= 1) {
        s  += __shfl_xor_sync(0xffffffffu, s, o);
        s2 += __shfl_xor_sync(0xffffffffu, s2, o);
    }
    __shared__ float sh[16];
    int w = tid >> 5;
    if ((tid & 31) == 0) { sh[w] = s; sh[8 + w] = s2; }
    __syncthreads();
    float S = 0.f, S2 = 0.f;
#pragma unroll
    for (int i = 0; i < 8; i++) { S += sh[i]; S2 += sh[8 + i]; }
    float mu = S * (1.f / DIM);
    float var = S2 * (1.f / DIM) - mu * mu;
    float inv = rsqrtf(var + 1e-5f);
    float* orow = out + (size_t)t * DIM;
#pragma unroll
    for (int i = 0; i < 4; i++) {
        int c = tid + i * 256;
        orow[c] = (v[i] - mu) * inv * lng[c] + lnb[c];
    }
}

// ---------------- load-balance loss --------------------------------------------
__global__ void k_loss(float* __restrict__ out, int out_size) {
    if (threadIdx.x == 0 && blockIdx.x == 0) {
        float lb = 0.f;
        const float invN = 1.f / (float)NTOK;
#pragma unroll
        for (int e = 0; e < NE; e++)
            lb += ((float)g_cnt[e] * invN) * (g_sumP[e] * invN);
        lb *= (float)NE;
        if (out_size > NTOK * DIM) out[NTOK * DIM] = lb;
    }
}

// ---------------- launch --------------------------------------------------------
extern "C" void kernel_launch(void* const* d_in, const int* in_sizes, int n_in,
                              void* d_out, int out_size) {
    const float* x   = (const float*)d_in[0];
    const float* rw  = (const float*)d_in[1];
    const float* gw  = (const float*)d_in[2];
    const float* uw  = (const float*)d_in[3];
    const float* dw  = (const float*)d_in[4];
    const float* lng = (const float*)d_in[5];
    const float* lnb = (const float*)d_in[6];
    float* out = (float*)d_out;
    (void)in_sizes; (void)n_in;

    static bool init_done = false;
    static cudaStream_t s1;
    static cudaEvent_t evFork, evJoin;
    if (!init_done) {
        cudaFuncSetAttribute(k_gemm1, cudaFuncAttributeMaxDynamicSharedMemorySize, 3 * ST1);
        cudaFuncSetAttribute(k_gemm2, cudaFuncAttributeMaxDynamicSharedMemorySize, 3 * ST2);
        cudaStreamCreateWithFlags(&s1, cudaStreamNonBlocking);
        cudaEventCreateWithFlags(&evFork, cudaEventDisableTiming);
        cudaEventCreateWithFlags(&evJoin, cudaEventDisableTiming);
        init_done = true;
    }

    __nv_bfloat16* wgT; cudaGetSymbolAddress((void**)&wgT, g_wgT);
    __nv_bfloat16* wuT; cudaGetSymbolAddress((void**)&wuT, g_wuT);
    __nv_bfloat16* wdT; cudaGetSymbolAddress((void**)&wdT, g_wdT);

    k_init<<<1, 32>>>();

    // fork: transposes on s1, token-side pipeline on default stream
    cudaEventRecord(evFork, 0);
    cudaStreamWaitEvent(s1, evFork, 0);
    k_transpose<<<dim3(FF / 32, DIM / 32, NE), 256, 0, s1>>>(gw, wgT, DIM, FF);
    k_transpose<<<dim3(FF / 32, DIM / 32, NE), 256, 0, s1>>>(uw, wuT, DIM, FF);
    k_transpose<<<dim3(DIM / 32, FF / 32, NE), 256, 0, s1>>>(dw, wdT, FF, DIM);
    cudaEventRecord(evJoin, s1);

    k_zero_ffn<<<4096, 256>>>();
    k_router<<<NTOK / 8, 256>>>(x, rw);
    k_scan<<<1, 256>>>();

    cudaStreamWaitEvent(0, evJoin, 0);

    k_gemm1<<<dim3(NE * NBM, FF / 128), 512, 3 * ST1>>>();
    k_gemm2<<<dim3(NE * NBM, DIM / 128), 256, 3 * ST2>>>();

    k_ln<<<NTOK, 256>>>(x, lng, lnb, out);
    k_loss<<<1, 1>>>(out, out_size);
}